// round 13
// baseline (speedup 1.0000x reference)
#include <cuda_runtime.h>
#include <cstdint>

#define Bn 32
#define Cc 256
#define Hh 56
#define Wd 56
#define HW 3136
#define NPIX (Bn*HW)
#define NELEM ((size_t)Bn*Cc*HW)

// ---- device scratch ----
__device__ uint4              g_xbits[NPIX * 2];        // 8 u32 per pixel
__device__ uint32_t           g_wbits[Cc * 9 * 8];      // [o][tap][8]
__device__ int                g_ctab[9 * Cc];           // [cfg][o] border corrections
__device__ unsigned long long g_ysum[Cc];
__device__ unsigned long long g_ysumsq[Cc];
__device__ short              g_y[NELEM];               // NCHW int16 conv result

__device__ __forceinline__ void FAf(uint32_t a, uint32_t b, uint32_t c,
                                    uint32_t& s, uint32_t& cy) {
    s  = a ^ b ^ c;
    cy = (a & b) | (c & (a ^ b));
}
__device__ __forceinline__ void HAf(uint32_t a, uint32_t b,
                                    uint32_t& s, uint32_t& cy) {
    s = a ^ b; cy = a & b;
}

// ---------------------------------------------------------------------------
// Kernel 1: binarize x (NCHW) -> per-pixel 256-bit vectors
// ---------------------------------------------------------------------------
__global__ void k_binarize_x(const float* __restrict__ x) {
    int gp = blockIdx.x * 256 + threadIdx.x;
    if (gp >= NPIX) return;
    int b = gp / HW;
    int p = gp - b * HW;
    const float* xp = x + (size_t)b * Cc * HW + p;
    uint32_t wrd[8];
#pragma unroll
    for (int j = 0; j < 8; j++) {
        uint32_t v = 0;
#pragma unroll
        for (int l = 0; l < 32; l++) {
            float f = xp[(size_t)(j * 32 + l) * HW];
            v |= (f > 0.0f ? 1u : 0u) << l;
        }
        wrd[j] = v;
    }
    g_xbits[gp * 2 + 0] = make_uint4(wrd[0], wrd[1], wrd[2], wrd[3]);
    g_xbits[gp * 2 + 1] = make_uint4(wrd[4], wrd[5], wrd[6], wrd[7]);
}

// ---------------------------------------------------------------------------
// Kernel 2 (fused): blocks 0..71 binarize W + zero stats; block 72 builds
// the border-correction table directly from Wt (independent of g_wbits).
// ---------------------------------------------------------------------------
__global__ void k_prep_w(const float* __restrict__ Wt) {
    if (blockIdx.x == 72) {
        int o = threadIdx.x;
        int ct[9];
#pragma unroll
        for (int t = 0; t < 9; t++) ct[t] = 0;
        const float* wp = Wt + (size_t)o * Cc * 9;
        for (int i = 0; i < Cc; i++) {
#pragma unroll
            for (int t = 0; t < 9; t++)
                ct[t] += (wp[i * 9 + t] > 0.f) ? 1 : 0;
        }
#pragma unroll
        for (int cfg = 0; cfg < 9; cfg++) {
            int rcf = cfg / 3, ccf = cfg % 3;
            int Cv = 0;
#pragma unroll
            for (int t = 0; t < 9; t++) {
                int kh = t / 3, kw = t % 3;
                bool inv = (rcf == 0 && kh == 0) || (rcf == 2 && kh == 2) ||
                           (ccf == 0 && kw == 0) || (ccf == 2 && kw == 2);
                if (inv) Cv += ct[t];
            }
            g_ctab[cfg * Cc + o] = Cv;
        }
        return;
    }
    int idx = blockIdx.x * 256 + threadIdx.x;
    if (idx < Cc) { g_ysum[idx] = 0ull; g_ysumsq[idx] = 0ull; }
    if (idx >= Cc * 9 * 8) return;
    int j   = idx & 7;
    int tap = (idx >> 3) % 9;
    int o   = idx / 72;
    uint32_t v = 0;
#pragma unroll
    for (int l = 0; l < 32; l++) {
        int i = j * 32 + l;
        float f = Wt[((size_t)o * Cc + i) * 9 + tap];
        v |= (f > 0.0f ? 1u : 0u) << l;
    }
    g_wbits[idx] = v;
}

// ---------------------------------------------------------------------------
// Kernel 3: XNOR conv — hybrid direct-POPC (taps 0..3) + CSA (taps 4..8)
// 128-thread blocks, 4 CTAs/SM -> 16 warps/SM (reg cap 124)
// ---------------------------------------------------------------------------
__global__ void __launch_bounds__(128, 4) k_conv() {
    const int p    = blockIdx.x * 128 + threadIdx.x;
    const int half = blockIdx.y;
    const int b    = blockIdx.z;

    __shared__ uint4 ws4[128 * 18];
    __shared__ int   sC[9 * 257];
    {
        const uint4* src = (const uint4*)(g_wbits + half * 128 * 72);
        for (int i = threadIdx.x; i < 128 * 18; i += 128) ws4[i] = src[i];
        for (int i = threadIdx.x; i < 9 * 256; i += 128)
            sC[(i >> 8) * 257 + (i & 255)] = g_ctab[i];
    }
    __syncthreads();
    if (p >= HW) return;

    const int h = p / Wd;
    const int w = p - h * Wd;
    const int rcf = (h == 0) ? 0 : ((h == Hh - 1) ? 2 : 1);
    const int ccf = (w == 0) ? 0 : ((w == Wd - 1) ? 2 : 1);
    const int nvbase = 256 * (((rcf == 1) ? 3 : 2) * ((ccf == 1) ? 3 : 2));
    const int cbase = (rcf * 3 + ccf) * 257 + half * 128;

    uint32_t xr[72];
#pragma unroll
    for (int kh = 0; kh < 3; kh++) {
#pragma unroll
        for (int kw = 0; kw < 3; kw++) {
            const int tap = kh * 3 + kw;
            const int hh = h + kh - 1, ww = w + kw - 1;
            const bool v = ((unsigned)hh < (unsigned)Hh) && ((unsigned)ww < (unsigned)Wd);
            if (v) {
                const uint4 a0 = g_xbits[(b * HW + hh * Wd + ww) * 2 + 0];
                const uint4 a1 = g_xbits[(b * HW + hh * Wd + ww) * 2 + 1];
                xr[tap * 8 + 0] = a0.x; xr[tap * 8 + 1] = a0.y;
                xr[tap * 8 + 2] = a0.z; xr[tap * 8 + 3] = a0.w;
                xr[tap * 8 + 4] = a1.x; xr[tap * 8 + 5] = a1.y;
                xr[tap * 8 + 6] = a1.z; xr[tap * 8 + 7] = a1.w;
            } else {
#pragma unroll
                for (int j = 0; j < 8; j++) xr[tap * 8 + j] = 0u;
            }
        }
    }

    short* yout = g_y + ((size_t)(b * Cc + half * 128)) * HW + p;

#pragma unroll 1
    for (int o = 0; o < 128; o++) {
        const uint4* wp = ws4 + o * 18;

        // ---- direct path: words 0..31 (taps 0..3), POPC unit ----
        int P1 = 0;
#pragma unroll
        for (int j = 0; j < 8; j++) {
            const uint4 v = wp[j];
            P1 += __popc(xr[4 * j + 0] ^ v.x) + __popc(xr[4 * j + 1] ^ v.y)
                + __popc(xr[4 * j + 2] ^ v.z) + __popc(xr[4 * j + 3] ^ v.w);
        }

        // ---- CSA path: words 32..71 (taps 4..8) ----
        uint32_t d[40];
#pragma unroll
        for (int j = 0; j < 10; j++) {
            const uint4 v = wp[8 + j];
            d[4 * j + 0] = xr[32 + 4 * j + 0] ^ v.x;
            d[4 * j + 1] = xr[32 + 4 * j + 1] ^ v.y;
            d[4 * j + 2] = xr[32 + 4 * j + 2] ^ v.z;
            d[4 * j + 3] = xr[32 + 4 * j + 3] ^ v.w;
        }
        uint32_t s1[13], c1[13];
#pragma unroll
        for (int g = 0; g < 13; g++)
            FAf(d[3 * g], d[3 * g + 1], d[3 * g + 2], s1[g], c1[g]);
        uint32_t t0, t1, t2, t3, u0, u1, u2, u3;
        FAf(s1[0], s1[1], s1[2],  t0, u0);
        FAf(s1[3], s1[4], s1[5],  t1, u1);
        FAf(s1[6], s1[7], s1[8],  t2, u2);
        FAf(s1[9], s1[10], s1[11], t3, u3);
        uint32_t v0, z0, v1, z1;
        FAf(t0, t1, t2, v0, z0);
        FAf(t3, s1[12], d[39], v1, z1);
        uint32_t e0, e1, e2, e3, e4, e5, f0, f1, f2, f3, f4, f5;
        FAf(c1[0], c1[1], c1[2],   e0, f0);
        FAf(c1[3], c1[4], c1[5],   e1, f1);
        FAf(c1[6], c1[7], c1[8],   e2, f2);
        FAf(c1[9], c1[10], c1[11], e3, f3);
        FAf(c1[12], u0, u1,        e4, f4);
        FAf(u2, u3, z0,            e5, f5);
        uint32_t g0, h0, g1, h1, k0, m0;
        FAf(e0, e1, e2, g0, h0);
        FAf(e3, e4, z1, g1, h1);
        FAf(g0, g1, e5, k0, m0);
        uint32_t r0, n0, r1, n1, r2, n2, a4, b4;
        FAf(f0, f1, f2, r0, n0);
        FAf(f3, f4, f5, r1, n1);
        FAf(h0, h1, m0, r2, n2);
        FAf(r0, r1, r2, a4, b4);
        uint32_t a8, b8, s8, c8, s16, c16;
        FAf(n0, n1, n2, a8, b8);
        HAf(a8, b4, s8, c8);
        HAf(b8, c8, s16, c16);

        int P = P1 + __popc(v0) + __popc(v1)
              + (__popc(k0)  << 1)
              + (__popc(a4)  << 2)
              + (__popc(s8)  << 3)
              + (__popc(s16) << 4)
              + (__popc(c16) << 5);
        int y = nvbase + 2 * sC[cbase + o] - 2 * P;
        yout[(size_t)o * HW] = (short)y;
    }
}

// ---------------------------------------------------------------------------
// Kernel 3b: BN statistics — 8 batches per block for deep MLP
// ---------------------------------------------------------------------------
__global__ void k_stats() {
    const int c  = blockIdx.x;
    const int b0 = blockIdx.y * 8;
    int       s  = 0;
    long long sq = 0;
#pragma unroll
    for (int bb = 0; bb < 8; bb++) {
        const int4* yp = (const int4*)(g_y + ((size_t)((b0 + bb) * Cc + c)) * HW);
        for (int i = threadIdx.x; i < HW / 8; i += 256) {
            int4 v = yp[i];
            const int ww[4] = {v.x, v.y, v.z, v.w};
#pragma unroll
            for (int j = 0; j < 4; j++) {
                int lo = (short)(ww[j] & 0xFFFF);
                int hi = (short)(((unsigned)ww[j]) >> 16);
                s  += lo + hi;
                sq += (long long)lo * lo + (long long)hi * hi;
            }
        }
    }
#pragma unroll
    for (int off = 16; off > 0; off >>= 1) {
        s  += __shfl_down_sync(0xFFFFFFFFu, s,  off);
        sq += __shfl_down_sync(0xFFFFFFFFu, sq, off);
    }
    __shared__ int       wsum[8];
    __shared__ long long wsq[8];
    const int lane = threadIdx.x & 31, wid = threadIdx.x >> 5;
    if (lane == 0) { wsum[wid] = s; wsq[wid] = sq; }
    __syncthreads();
    if (wid == 0) {
        int       s2  = (lane < 8) ? wsum[lane] : 0;
        long long sq2 = (lane < 8) ? wsq[lane]  : 0;
#pragma unroll
        for (int off = 4; off > 0; off >>= 1) {
            s2  += __shfl_down_sync(0xFFFFFFFFu, s2,  off);
            sq2 += __shfl_down_sync(0xFFFFFFFFu, sq2, off);
        }
        if (lane == 0) {
            atomicAdd(&g_ysum[c],   (unsigned long long)(long long)s2);
            atomicAdd(&g_ysumsq[c], (unsigned long long)sq2);
        }
    }
}

// ---------------------------------------------------------------------------
// Kernel 4: BN finalize (inline) + apply + residual, vec4, 32-bit indexing
// ---------------------------------------------------------------------------
__global__ void k_bn_add(const float* __restrict__ x,
                         const float* __restrict__ gamma,
                         const float* __restrict__ beta,
                         float* __restrict__ out) {
    unsigned i4 = blockIdx.x * 256u + threadIdx.x;
    if (i4 >= (unsigned)(NELEM / 4)) return;
    unsigned e4 = i4 * 4u;                  // element index (fits 32-bit)
    int c = (int)((e4 / HW) % Cc);
    const float ninv = 1.0f / (float)NPIX;
    float mean = (float)(long long)g_ysum[c] * ninv;
    float var  = (float)(long long)g_ysumsq[c] * ninv - mean * mean;
    float inv  = gamma[c] * rsqrtf(var + 1e-5f);
    float bias = beta[c] - mean * inv;
    short4 ys = ((const short4*)g_y)[i4];
    float4 xv = ((const float4*)x)[i4];
    float4 ov;
    ov.x = (float)ys.x * inv + bias + xv.x;
    ov.y = (float)ys.y * inv + bias + xv.y;
    ov.z = (float)ys.z * inv + bias + xv.z;
    ov.w = (float)ys.w * inv + bias + xv.w;
    ((float4*)out)[i4] = ov;
}

// ---------------------------------------------------------------------------
extern "C" void kernel_launch(void* const* d_in, const int* in_sizes, int n_in,
                              void* d_out, int out_size) {
    const float* x     = (const float*)d_in[0];
    const float* Wt    = (const float*)d_in[1];
    const float* gamma = (const float*)d_in[2];
    const float* beta  = (const float*)d_in[3];
    float* out = (float*)d_out;

    k_binarize_x<<<(NPIX + 255) / 256, 256>>>(x);
    k_prep_w<<<73, 256>>>(Wt);             // fused wbits + ctab + stat zeroing
    k_conv<<<dim3((HW + 127) / 128, 2, Bn), 128>>>();
    k_stats<<<dim3(Cc, Bn / 8), 256>>>();
    k_bn_add<<<(unsigned)(NELEM / 4 + 255) / 256, 256>>>(x, gamma, beta, out);
}

// round 14
// speedup vs baseline: 1.0423x; 1.0423x over previous
#include <cuda_runtime.h>
#include <cstdint>

#define Bn 32
#define Cc 256
#define Hh 56
#define Wd 56
#define HW 3136
#define NPIX (Bn*HW)
#define NELEM ((size_t)Bn*Cc*HW)

// ---- device scratch ----
__device__ uint4              g_xbits[NPIX * 2];        // 8 u32 per pixel
__device__ uint32_t           g_wbits[Cc * 9 * 8];      // [o][tap][8]
__device__ int                g_ctab[9 * Cc];           // [cfg][o] border corrections
__device__ unsigned long long g_ysum[Cc];
__device__ unsigned long long g_ysumsq[Cc];
__device__ short              g_y[NELEM];               // NCHW int16 conv result

__device__ __forceinline__ void FAf(uint32_t a, uint32_t b, uint32_t c,
                                    uint32_t& s, uint32_t& cy) {
    s  = a ^ b ^ c;
    cy = (a & b) | (c & (a ^ b));
}
__device__ __forceinline__ void HAf(uint32_t a, uint32_t b,
                                    uint32_t& s, uint32_t& cy) {
    s = a ^ b; cy = a & b;
}

// ---------------------------------------------------------------------------
// Kernel 1: binarize x (NCHW) -> per-pixel 256-bit vectors
// ---------------------------------------------------------------------------
__global__ void k_binarize_x(const float* __restrict__ x) {
    int gp = blockIdx.x * 256 + threadIdx.x;
    if (gp >= NPIX) return;
    int b = gp / HW;
    int p = gp - b * HW;
    const float* xp = x + (size_t)b * Cc * HW + p;
    uint32_t wrd[8];
#pragma unroll
    for (int j = 0; j < 8; j++) {
        uint32_t v = 0;
#pragma unroll
        for (int l = 0; l < 32; l++) {
            float f = xp[(size_t)(j * 32 + l) * HW];
            v |= (f > 0.0f ? 1u : 0u) << l;
        }
        wrd[j] = v;
    }
    g_xbits[gp * 2 + 0] = make_uint4(wrd[0], wrd[1], wrd[2], wrd[3]);
    g_xbits[gp * 2 + 1] = make_uint4(wrd[4], wrd[5], wrd[6], wrd[7]);
}

// ---------------------------------------------------------------------------
// Kernel 2 (fused): blocks 0..71 binarize W + zero stats; block 72 builds
// the border-correction table directly from Wt (independent of g_wbits).
// ---------------------------------------------------------------------------
__global__ void k_prep_w(const float* __restrict__ Wt) {
    if (blockIdx.x == 72) {
        int o = threadIdx.x;
        int ct[9];
#pragma unroll
        for (int t = 0; t < 9; t++) ct[t] = 0;
        const float* wp = Wt + (size_t)o * Cc * 9;
        for (int i = 0; i < Cc; i++) {
#pragma unroll
            for (int t = 0; t < 9; t++)
                ct[t] += (wp[i * 9 + t] > 0.f) ? 1 : 0;
        }
#pragma unroll
        for (int cfg = 0; cfg < 9; cfg++) {
            int rcf = cfg / 3, ccf = cfg % 3;
            int Cv = 0;
#pragma unroll
            for (int t = 0; t < 9; t++) {
                int kh = t / 3, kw = t % 3;
                bool inv = (rcf == 0 && kh == 0) || (rcf == 2 && kh == 2) ||
                           (ccf == 0 && kw == 0) || (ccf == 2 && kw == 2);
                if (inv) Cv += ct[t];
            }
            g_ctab[cfg * Cc + o] = Cv;
        }
        return;
    }
    int idx = blockIdx.x * 256 + threadIdx.x;
    if (idx < Cc) { g_ysum[idx] = 0ull; g_ysumsq[idx] = 0ull; }
    if (idx >= Cc * 9 * 8) return;
    int j   = idx & 7;
    int tap = (idx >> 3) % 9;
    int o   = idx / 72;
    uint32_t v = 0;
#pragma unroll
    for (int l = 0; l < 32; l++) {
        int i = j * 32 + l;
        float f = Wt[((size_t)o * Cc + i) * 9 + tap];
        v |= (f > 0.0f ? 1u : 0u) << l;
    }
    g_wbits[idx] = v;
}

// ---------------------------------------------------------------------------
// Kernel 3: XNOR conv — hybrid direct-POPC (taps 0..3) + CSA (taps 4..8)
// 128-thread blocks, 3 CTAs/SM (champion configuration, ~139 regs, no spills)
// ---------------------------------------------------------------------------
__global__ void __launch_bounds__(128, 3) k_conv() {
    const int p    = blockIdx.x * 128 + threadIdx.x;
    const int half = blockIdx.y;
    const int b    = blockIdx.z;

    __shared__ uint4 ws4[128 * 18];
    __shared__ int   sC[9 * 257];
    {
        const uint4* src = (const uint4*)(g_wbits + half * 128 * 72);
        for (int i = threadIdx.x; i < 128 * 18; i += 128) ws4[i] = src[i];
        for (int i = threadIdx.x; i < 9 * 256; i += 128)
            sC[(i >> 8) * 257 + (i & 255)] = g_ctab[i];
    }
    __syncthreads();
    if (p >= HW) return;

    const int h = p / Wd;
    const int w = p - h * Wd;
    const int rcf = (h == 0) ? 0 : ((h == Hh - 1) ? 2 : 1);
    const int ccf = (w == 0) ? 0 : ((w == Wd - 1) ? 2 : 1);
    const int nvbase = 256 * (((rcf == 1) ? 3 : 2) * ((ccf == 1) ? 3 : 2));
    const int cbase = (rcf * 3 + ccf) * 257 + half * 128;

    uint32_t xr[72];
#pragma unroll
    for (int kh = 0; kh < 3; kh++) {
#pragma unroll
        for (int kw = 0; kw < 3; kw++) {
            const int tap = kh * 3 + kw;
            const int hh = h + kh - 1, ww = w + kw - 1;
            const bool v = ((unsigned)hh < (unsigned)Hh) && ((unsigned)ww < (unsigned)Wd);
            if (v) {
                const uint4 a0 = g_xbits[(b * HW + hh * Wd + ww) * 2 + 0];
                const uint4 a1 = g_xbits[(b * HW + hh * Wd + ww) * 2 + 1];
                xr[tap * 8 + 0] = a0.x; xr[tap * 8 + 1] = a0.y;
                xr[tap * 8 + 2] = a0.z; xr[tap * 8 + 3] = a0.w;
                xr[tap * 8 + 4] = a1.x; xr[tap * 8 + 5] = a1.y;
                xr[tap * 8 + 6] = a1.z; xr[tap * 8 + 7] = a1.w;
            } else {
#pragma unroll
                for (int j = 0; j < 8; j++) xr[tap * 8 + j] = 0u;
            }
        }
    }

    short* yout = g_y + ((size_t)(b * Cc + half * 128)) * HW + p;

#pragma unroll 1
    for (int o = 0; o < 128; o++) {
        const uint4* wp = ws4 + o * 18;

        // ---- direct path: words 0..31 (taps 0..3), POPC unit ----
        int P1 = 0;
#pragma unroll
        for (int j = 0; j < 8; j++) {
            const uint4 v = wp[j];
            P1 += __popc(xr[4 * j + 0] ^ v.x) + __popc(xr[4 * j + 1] ^ v.y)
                + __popc(xr[4 * j + 2] ^ v.z) + __popc(xr[4 * j + 3] ^ v.w);
        }

        // ---- CSA path: words 32..71 (taps 4..8) ----
        uint32_t d[40];
#pragma unroll
        for (int j = 0; j < 10; j++) {
            const uint4 v = wp[8 + j];
            d[4 * j + 0] = xr[32 + 4 * j + 0] ^ v.x;
            d[4 * j + 1] = xr[32 + 4 * j + 1] ^ v.y;
            d[4 * j + 2] = xr[32 + 4 * j + 2] ^ v.z;
            d[4 * j + 3] = xr[32 + 4 * j + 3] ^ v.w;
        }
        uint32_t s1[13], c1[13];
#pragma unroll
        for (int g = 0; g < 13; g++)
            FAf(d[3 * g], d[3 * g + 1], d[3 * g + 2], s1[g], c1[g]);
        uint32_t t0, t1, t2, t3, u0, u1, u2, u3;
        FAf(s1[0], s1[1], s1[2],  t0, u0);
        FAf(s1[3], s1[4], s1[5],  t1, u1);
        FAf(s1[6], s1[7], s1[8],  t2, u2);
        FAf(s1[9], s1[10], s1[11], t3, u3);
        uint32_t v0, z0, v1, z1;
        FAf(t0, t1, t2, v0, z0);
        FAf(t3, s1[12], d[39], v1, z1);
        uint32_t e0, e1, e2, e3, e4, e5, f0, f1, f2, f3, f4, f5;
        FAf(c1[0], c1[1], c1[2],   e0, f0);
        FAf(c1[3], c1[4], c1[5],   e1, f1);
        FAf(c1[6], c1[7], c1[8],   e2, f2);
        FAf(c1[9], c1[10], c1[11], e3, f3);
        FAf(c1[12], u0, u1,        e4, f4);
        FAf(u2, u3, z0,            e5, f5);
        uint32_t g0, h0, g1, h1, k0, m0;
        FAf(e0, e1, e2, g0, h0);
        FAf(e3, e4, z1, g1, h1);
        FAf(g0, g1, e5, k0, m0);
        uint32_t r0, n0, r1, n1, r2, n2, a4, b4;
        FAf(f0, f1, f2, r0, n0);
        FAf(f3, f4, f5, r1, n1);
        FAf(h0, h1, m0, r2, n2);
        FAf(r0, r1, r2, a4, b4);
        uint32_t a8, b8, s8, c8, s16, c16;
        FAf(n0, n1, n2, a8, b8);
        HAf(a8, b4, s8, c8);
        HAf(b8, c8, s16, c16);

        int P = P1 + __popc(v0) + __popc(v1)
              + (__popc(k0)  << 1)
              + (__popc(a4)  << 2)
              + (__popc(s8)  << 3)
              + (__popc(s16) << 4)
              + (__popc(c16) << 5);
        int y = nvbase + 2 * sC[cbase + o] - 2 * P;
        yout[(size_t)o * HW] = (short)y;
    }
}

// ---------------------------------------------------------------------------
// Kernel 3b: BN statistics — 8 batches per block for deep MLP
// ---------------------------------------------------------------------------
__global__ void k_stats() {
    const int c  = blockIdx.x;
    const int b0 = blockIdx.y * 8;
    int       s  = 0;
    long long sq = 0;
#pragma unroll
    for (int bb = 0; bb < 8; bb++) {
        const int4* yp = (const int4*)(g_y + ((size_t)((b0 + bb) * Cc + c)) * HW);
        for (int i = threadIdx.x; i < HW / 8; i += 256) {
            int4 v = yp[i];
            const int ww[4] = {v.x, v.y, v.z, v.w};
#pragma unroll
            for (int j = 0; j < 4; j++) {
                int lo = (short)(ww[j] & 0xFFFF);
                int hi = (short)(((unsigned)ww[j]) >> 16);
                s  += lo + hi;
                sq += (long long)lo * lo + (long long)hi * hi;
            }
        }
    }
#pragma unroll
    for (int off = 16; off > 0; off >>= 1) {
        s  += __shfl_down_sync(0xFFFFFFFFu, s,  off);
        sq += __shfl_down_sync(0xFFFFFFFFu, sq, off);
    }
    __shared__ int       wsum[8];
    __shared__ long long wsq[8];
    const int lane = threadIdx.x & 31, wid = threadIdx.x >> 5;
    if (lane == 0) { wsum[wid] = s; wsq[wid] = sq; }
    __syncthreads();
    if (wid == 0) {
        int       s2  = (lane < 8) ? wsum[lane] : 0;
        long long sq2 = (lane < 8) ? wsq[lane]  : 0;
#pragma unroll
        for (int off = 4; off > 0; off >>= 1) {
            s2  += __shfl_down_sync(0xFFFFFFFFu, s2,  off);
            sq2 += __shfl_down_sync(0xFFFFFFFFu, sq2, off);
        }
        if (lane == 0) {
            atomicAdd(&g_ysum[c],   (unsigned long long)(long long)s2);
            atomicAdd(&g_ysumsq[c], (unsigned long long)sq2);
        }
    }
}

// ---------------------------------------------------------------------------
// Kernel 4: BN finalize (inline) + apply + residual, vec4, 32-bit indexing
// ---------------------------------------------------------------------------
__global__ void k_bn_add(const float* __restrict__ x,
                         const float* __restrict__ gamma,
                         const float* __restrict__ beta,
                         float* __restrict__ out) {
    unsigned i4 = blockIdx.x * 256u + threadIdx.x;
    if (i4 >= (unsigned)(NELEM / 4)) return;
    unsigned e4 = i4 * 4u;
    int c = (int)((e4 / HW) % Cc);
    const float ninv = 1.0f / (float)NPIX;
    float mean = (float)(long long)g_ysum[c] * ninv;
    float var  = (float)(long long)g_ysumsq[c] * ninv - mean * mean;
    float inv  = gamma[c] * rsqrtf(var + 1e-5f);
    float bias = beta[c] - mean * inv;
    short4 ys = ((const short4*)g_y)[i4];
    float4 xv = ((const float4*)x)[i4];
    float4 ov;
    ov.x = (float)ys.x * inv + bias + xv.x;
    ov.y = (float)ys.y * inv + bias + xv.y;
    ov.z = (float)ys.z * inv + bias + xv.z;
    ov.w = (float)ys.w * inv + bias + xv.w;
    ((float4*)out)[i4] = ov;
}

// ---------------------------------------------------------------------------
extern "C" void kernel_launch(void* const* d_in, const int* in_sizes, int n_in,
                              void* d_out, int out_size) {
    const float* x     = (const float*)d_in[0];
    const float* Wt    = (const float*)d_in[1];
    const float* gamma = (const float*)d_in[2];
    const float* beta  = (const float*)d_in[3];
    float* out = (float*)d_out;

    k_binarize_x<<<(NPIX + 255) / 256, 256>>>(x);
    k_prep_w<<<73, 256>>>(Wt);
    k_conv<<<dim3((HW + 127) / 128, 2, Bn), 128>>>();
    k_stats<<<dim3(Cc, Bn / 8), 256>>>();
    k_bn_add<<<(unsigned)(NELEM / 4 + 255) / 256, 256>>>(x, gamma, beta, out);
}

// round 15
// speedup vs baseline: 1.8248x; 1.7507x over previous
#include <cuda_runtime.h>
#include <cstdint>

#define Bn 32
#define Cc 256
#define Hh 56
#define Wd 56
#define HW 3136
#define NPIX (Bn*HW)
#define NELEM ((size_t)Bn*Cc*HW)

// ---- device scratch ----
__device__ uint4              g_xbits[NPIX * 2];        // 8 u32 per pixel
__device__ uint32_t           g_wbits[Cc * 9 * 8];      // [o][tap][8]
__device__ int                g_ctab[9 * Cc];           // [cfg][o] border corrections
__device__ unsigned long long g_ysum[Cc];
__device__ unsigned long long g_ysumsq[Cc];
__device__ short              g_y[NELEM];               // NCHW int16 conv result

__device__ __forceinline__ void FAf(uint32_t a, uint32_t b, uint32_t c,
                                    uint32_t& s, uint32_t& cy) {
    s  = a ^ b ^ c;
    cy = (a & b) | (c & (a ^ b));
}
__device__ __forceinline__ void HAf(uint32_t a, uint32_t b,
                                    uint32_t& s, uint32_t& cy) {
    s = a ^ b; cy = a & b;
}

// ---------------------------------------------------------------------------
// Kernel 1: binarize x (NCHW) -> per-pixel 256-bit vectors
// ---------------------------------------------------------------------------
__global__ void k_binarize_x(const float* __restrict__ x) {
    int gp = blockIdx.x * 256 + threadIdx.x;
    if (gp >= NPIX) return;
    int b = gp / HW;
    int p = gp - b * HW;
    const float* xp = x + (size_t)b * Cc * HW + p;
    uint32_t wrd[8];
#pragma unroll
    for (int j = 0; j < 8; j++) {
        uint32_t v = 0;
#pragma unroll
        for (int l = 0; l < 32; l++) {
            float f = xp[(size_t)(j * 32 + l) * HW];
            v |= (f > 0.0f ? 1u : 0u) << l;
        }
        wrd[j] = v;
    }
    g_xbits[gp * 2 + 0] = make_uint4(wrd[0], wrd[1], wrd[2], wrd[3]);
    g_xbits[gp * 2 + 1] = make_uint4(wrd[4], wrd[5], wrd[6], wrd[7]);
}

// ---------------------------------------------------------------------------
// Kernel 2: binarize W (OIHW) + zero stat accumulators (coalesced across tid)
// ---------------------------------------------------------------------------
__global__ void k_binarize_w(const float* __restrict__ Wt) {
    int idx = blockIdx.x * 256 + threadIdx.x;
    if (idx < Cc) { g_ysum[idx] = 0ull; g_ysumsq[idx] = 0ull; }
    if (idx >= Cc * 9 * 8) return;
    int j   = idx & 7;
    int tap = (idx >> 3) % 9;
    int o   = idx / 72;
    uint32_t v = 0;
#pragma unroll
    for (int l = 0; l < 32; l++) {
        int i = j * 32 + l;
        float f = Wt[((size_t)o * Cc + i) * 9 + tap];
        v |= (f > 0.0f ? 1u : 0u) << l;
    }
    g_wbits[idx] = v;
}

// ---------------------------------------------------------------------------
// Kernel 2b: per (border-config, outch) correction table from PACKED bits
// (18 KB read; cheap single block — measured fine in champion)
// ---------------------------------------------------------------------------
__global__ void k_prep_c() {
    int o = threadIdx.x;
    int ct[9];
#pragma unroll
    for (int t = 0; t < 9; t++) {
        int s = 0;
#pragma unroll
        for (int j = 0; j < 8; j++) s += __popc(g_wbits[o * 72 + t * 8 + j]);
        ct[t] = s;
    }
#pragma unroll
    for (int cfg = 0; cfg < 9; cfg++) {
        int rcf = cfg / 3, ccf = cfg % 3;
        int Cv = 0;
#pragma unroll
        for (int t = 0; t < 9; t++) {
            int kh = t / 3, kw = t % 3;
            bool inv = (rcf == 0 && kh == 0) || (rcf == 2 && kh == 2) ||
                       (ccf == 0 && kw == 0) || (ccf == 2 && kw == 2);
            if (inv) Cv += ct[t];
        }
        g_ctab[cfg * Cc + o] = Cv;
    }
}

// ---------------------------------------------------------------------------
// Kernel 3: XNOR conv — hybrid direct-POPC (taps 0..3) + CSA (taps 4..8)
// 128-thread blocks, 3 CTAs/SM (champion configuration)
// ---------------------------------------------------------------------------
__global__ void __launch_bounds__(128, 3) k_conv() {
    const int p    = blockIdx.x * 128 + threadIdx.x;
    const int half = blockIdx.y;
    const int b    = blockIdx.z;

    __shared__ uint4 ws4[128 * 18];
    __shared__ int   sC[9 * 257];
    {
        const uint4* src = (const uint4*)(g_wbits + half * 128 * 72);
        for (int i = threadIdx.x; i < 128 * 18; i += 128) ws4[i] = src[i];
        for (int i = threadIdx.x; i < 9 * 256; i += 128)
            sC[(i >> 8) * 257 + (i & 255)] = g_ctab[i];
    }
    __syncthreads();
    if (p >= HW) return;

    const int h = p / Wd;
    const int w = p - h * Wd;
    const int rcf = (h == 0) ? 0 : ((h == Hh - 1) ? 2 : 1);
    const int ccf = (w == 0) ? 0 : ((w == Wd - 1) ? 2 : 1);
    const int nvbase = 256 * (((rcf == 1) ? 3 : 2) * ((ccf == 1) ? 3 : 2));
    const int cbase = (rcf * 3 + ccf) * 257 + half * 128;

    uint32_t xr[72];
#pragma unroll
    for (int kh = 0; kh < 3; kh++) {
#pragma unroll
        for (int kw = 0; kw < 3; kw++) {
            const int tap = kh * 3 + kw;
            const int hh = h + kh - 1, ww = w + kw - 1;
            const bool v = ((unsigned)hh < (unsigned)Hh) && ((unsigned)ww < (unsigned)Wd);
            if (v) {
                const uint4 a0 = g_xbits[(b * HW + hh * Wd + ww) * 2 + 0];
                const uint4 a1 = g_xbits[(b * HW + hh * Wd + ww) * 2 + 1];
                xr[tap * 8 + 0] = a0.x; xr[tap * 8 + 1] = a0.y;
                xr[tap * 8 + 2] = a0.z; xr[tap * 8 + 3] = a0.w;
                xr[tap * 8 + 4] = a1.x; xr[tap * 8 + 5] = a1.y;
                xr[tap * 8 + 6] = a1.z; xr[tap * 8 + 7] = a1.w;
            } else {
#pragma unroll
                for (int j = 0; j < 8; j++) xr[tap * 8 + j] = 0u;
            }
        }
    }

    short* yout = g_y + ((size_t)(b * Cc + half * 128)) * HW + p;

#pragma unroll 1
    for (int o = 0; o < 128; o++) {
        const uint4* wp = ws4 + o * 18;

        // ---- direct path: words 0..31 (taps 0..3), POPC unit ----
        int P1 = 0;
#pragma unroll
        for (int j = 0; j < 8; j++) {
            const uint4 v = wp[j];
            P1 += __popc(xr[4 * j + 0] ^ v.x) + __popc(xr[4 * j + 1] ^ v.y)
                + __popc(xr[4 * j + 2] ^ v.z) + __popc(xr[4 * j + 3] ^ v.w);
        }

        // ---- CSA path: words 32..71 (taps 4..8) ----
        uint32_t d[40];
#pragma unroll
        for (int j = 0; j < 10; j++) {
            const uint4 v = wp[8 + j];
            d[4 * j + 0] = xr[32 + 4 * j + 0] ^ v.x;
            d[4 * j + 1] = xr[32 + 4 * j + 1] ^ v.y;
            d[4 * j + 2] = xr[32 + 4 * j + 2] ^ v.z;
            d[4 * j + 3] = xr[32 + 4 * j + 3] ^ v.w;
        }
        uint32_t s1[13], c1[13];
#pragma unroll
        for (int g = 0; g < 13; g++)
            FAf(d[3 * g], d[3 * g + 1], d[3 * g + 2], s1[g], c1[g]);
        uint32_t t0, t1, t2, t3, u0, u1, u2, u3;
        FAf(s1[0], s1[1], s1[2],  t0, u0);
        FAf(s1[3], s1[4], s1[5],  t1, u1);
        FAf(s1[6], s1[7], s1[8],  t2, u2);
        FAf(s1[9], s1[10], s1[11], t3, u3);
        uint32_t v0, z0, v1, z1;
        FAf(t0, t1, t2, v0, z0);
        FAf(t3, s1[12], d[39], v1, z1);
        uint32_t e0, e1, e2, e3, e4, e5, f0, f1, f2, f3, f4, f5;
        FAf(c1[0], c1[1], c1[2],   e0, f0);
        FAf(c1[3], c1[4], c1[5],   e1, f1);
        FAf(c1[6], c1[7], c1[8],   e2, f2);
        FAf(c1[9], c1[10], c1[11], e3, f3);
        FAf(c1[12], u0, u1,        e4, f4);
        FAf(u2, u3, z0,            e5, f5);
        uint32_t g0, h0, g1, h1, k0, m0;
        FAf(e0, e1, e2, g0, h0);
        FAf(e3, e4, z1, g1, h1);
        FAf(g0, g1, e5, k0, m0);
        uint32_t r0, n0, r1, n1, r2, n2, a4, b4;
        FAf(f0, f1, f2, r0, n0);
        FAf(f3, f4, f5, r1, n1);
        FAf(h0, h1, m0, r2, n2);
        FAf(r0, r1, r2, a4, b4);
        uint32_t a8, b8, s8, c8, s16, c16;
        FAf(n0, n1, n2, a8, b8);
        HAf(a8, b4, s8, c8);
        HAf(b8, c8, s16, c16);

        int P = P1 + __popc(v0) + __popc(v1)
              + (__popc(k0)  << 1)
              + (__popc(a4)  << 2)
              + (__popc(s8)  << 3)
              + (__popc(s16) << 4)
              + (__popc(c16) << 5);
        int y = nvbase + 2 * sC[cbase + o] - 2 * P;
        yout[(size_t)o * HW] = (short)y;
    }
}

// ---------------------------------------------------------------------------
// Kernel 3b: BN statistics — 8 batches per block for deep MLP
// ---------------------------------------------------------------------------
__global__ void k_stats() {
    const int c  = blockIdx.x;
    const int b0 = blockIdx.y * 8;
    int       s  = 0;
    long long sq = 0;
#pragma unroll
    for (int bb = 0; bb < 8; bb++) {
        const int4* yp = (const int4*)(g_y + ((size_t)((b0 + bb) * Cc + c)) * HW);
        for (int i = threadIdx.x; i < HW / 8; i += 256) {
            int4 v = yp[i];
            const int ww[4] = {v.x, v.y, v.z, v.w};
#pragma unroll
            for (int j = 0; j < 4; j++) {
                int lo = (short)(ww[j] & 0xFFFF);
                int hi = (short)(((unsigned)ww[j]) >> 16);
                s  += lo + hi;
                sq += (long long)lo * lo + (long long)hi * hi;
            }
        }
    }
#pragma unroll
    for (int off = 16; off > 0; off >>= 1) {
        s  += __shfl_down_sync(0xFFFFFFFFu, s,  off);
        sq += __shfl_down_sync(0xFFFFFFFFu, sq, off);
    }
    __shared__ int       wsum[8];
    __shared__ long long wsq[8];
    const int lane = threadIdx.x & 31, wid = threadIdx.x >> 5;
    if (lane == 0) { wsum[wid] = s; wsq[wid] = sq; }
    __syncthreads();
    if (wid == 0) {
        int       s2  = (lane < 8) ? wsum[lane] : 0;
        long long sq2 = (lane < 8) ? wsq[lane]  : 0;
#pragma unroll
        for (int off = 4; off > 0; off >>= 1) {
            s2  += __shfl_down_sync(0xFFFFFFFFu, s2,  off);
            sq2 += __shfl_down_sync(0xFFFFFFFFu, sq2, off);
        }
        if (lane == 0) {
            atomicAdd(&g_ysum[c],   (unsigned long long)(long long)s2);
            atomicAdd(&g_ysumsq[c], (unsigned long long)sq2);
        }
    }
}

// ---------------------------------------------------------------------------
// Kernel 4: BN finalize (inline) + apply + residual, vec4, 32-bit indexing
// ---------------------------------------------------------------------------
__global__ void k_bn_add(const float* __restrict__ x,
                         const float* __restrict__ gamma,
                         const float* __restrict__ beta,
                         float* __restrict__ out) {
    unsigned i4 = blockIdx.x * 256u + threadIdx.x;
    if (i4 >= (unsigned)(NELEM / 4)) return;
    unsigned e4 = i4 * 4u;
    int c = (int)((e4 / HW) % Cc);
    const float ninv = 1.0f / (float)NPIX;
    float mean = (float)(long long)g_ysum[c] * ninv;
    float var  = (float)(long long)g_ysumsq[c] * ninv - mean * mean;
    float inv  = gamma[c] * rsqrtf(var + 1e-5f);
    float bias = beta[c] - mean * inv;
    short4 ys = ((const short4*)g_y)[i4];
    float4 xv = ((const float4*)x)[i4];
    float4 ov;
    ov.x = (float)ys.x * inv + bias + xv.x;
    ov.y = (float)ys.y * inv + bias + xv.y;
    ov.z = (float)ys.z * inv + bias + xv.z;
    ov.w = (float)ys.w * inv + bias + xv.w;
    ((float4*)out)[i4] = ov;
}

// ---------------------------------------------------------------------------
extern "C" void kernel_launch(void* const* d_in, const int* in_sizes, int n_in,
                              void* d_out, int out_size) {
    const float* x     = (const float*)d_in[0];
    const float* Wt    = (const float*)d_in[1];
    const float* gamma = (const float*)d_in[2];
    const float* beta  = (const float*)d_in[3];
    float* out = (float*)d_out;

    k_binarize_x<<<(NPIX + 255) / 256, 256>>>(x);
    k_binarize_w<<<(Cc * 9 * 8 + 255) / 256, 256>>>(Wt);
    k_prep_c<<<1, 256>>>();
    k_conv<<<dim3((HW + 127) / 128, 2, Bn), 128>>>();
    k_stats<<<dim3(Cc, Bn / 8), 256>>>();
    k_bn_add<<<(unsigned)(NELEM / 4 + 255) / 256, 256>>>(x, gamma, beta, out);
}